// round 4
// baseline (speedup 1.0000x reference)
#include <cuda_runtime.h>
#include <math.h>

#define BATCH 64
#define Hh 512
#define Ww 512
#define NPIX (Hh * Ww)
#define NELEM (NPIX * 3)
#define MAGv 0.5f
#define ENHv (1.0f + 0.9f * MAGv)      // 1.45
#define FILLv 0.5f
#define INV_NELEM (1.0f / (float)NELEM)

// Tile geometry
#define TS 16                  // 16x16 output tile, 256 threads
#define RAW_P 32               // raw smem box pitch (pixels)
#define L0_P 24                // L0 smem box pitch (pixels)

__device__ float g_sumA[BATCH];   // sum of input (op0 == contrast)
__device__ float g_sumB[BATCH];   // sum of layer-0 output (op1 == contrast)

__device__ __forceinline__ float clip01(float v) {
    return fminf(fmaxf(v, 0.0f), 1.0f);
}

__device__ __forceinline__ void affineCoef(int op, float s,
        float& A, float& B, float& TX, float& C, float& D, float& TY) {
    A = 1.0f; B = 0.0f; TX = 0.0f; C = 0.0f; D = 1.0f; TY = 0.0f;
    if (op == 0) {
        float th = s * (30.0f * MAGv) * (3.14159265358979323846f / 180.0f);
        float si, co;
        sincosf(th, &si, &co);
        A = co; B = si; C = -si; D = co;
    } else if (op == 1) {
        B = -(s * 0.3f * MAGv);
    } else if (op == 2) {
        C = -(s * 0.3f * MAGv);
    } else if (op == 3) {
        TX = -(s * 0.3f * MAGv * (float)Ww);
    } else if (op == 4) {
        TY = -(s * 0.3f * MAGv * (float)Hh);
    }
}

// ---------------- global-memory L0 eval (used only by meanB prepass) ----------
struct L0P {
    int op;
    float A, Bc, TX, C, D, TY, f, m;
};

__device__ __forceinline__ float3 tap3g(const float* __restrict__ img, int yy, int xx) {
    if ((unsigned)xx >= (unsigned)Ww || (unsigned)yy >= (unsigned)Hh)
        return make_float3(FILLv, FILLv, FILLv);
    const float* p = img + (yy * Ww + xx) * 3;
    return make_float3(__ldg(p), __ldg(p + 1), __ldg(p + 2));
}

__device__ __forceinline__ float3 evalL0g(const float* __restrict__ img, const L0P P,
                                          int y, int x) {
    if (P.op < 5) {
        const float cx = 255.5f, cy = 255.5f;
        float xi = P.A * ((float)x - cx) + P.Bc * ((float)y - cy) + P.TX + cx;
        float yi = P.C * ((float)x - cx) + P.D * ((float)y - cy) + P.TY + cy;
        float x0 = floorf(xi), y0 = floorf(yi);
        float wx = xi - x0, wy = yi - y0;
        int ix = (int)x0, iy = (int)y0;
        float w00 = (1.0f - wx) * (1.0f - wy), w10 = wx * (1.0f - wy);
        float w01 = (1.0f - wx) * wy, w11 = wx * wy;
        float3 v00 = tap3g(img, iy, ix), v10 = tap3g(img, iy, ix + 1);
        float3 v01 = tap3g(img, iy + 1, ix), v11 = tap3g(img, iy + 1, ix + 1);
        return make_float3(v00.x * w00 + v10.x * w10 + v01.x * w01 + v11.x * w11,
                           v00.y * w00 + v10.y * w10 + v01.y * w01 + v11.y * w11,
                           v00.z * w00 + v10.z * w10 + v01.z * w01 + v11.z * w11);
    } else if (P.op == 5) {
        const float* p = img + (y * Ww + x) * 3;
        return make_float3(clip01(P.f * __ldg(p)), clip01(P.f * __ldg(p + 1)),
                           clip01(P.f * __ldg(p + 2)));
    } else if (P.op == 6) {
        const float* p = img + (y * Ww + x) * 3;
        return make_float3(clip01(P.m + P.f * (__ldg(p) - P.m)),
                           clip01(P.m + P.f * (__ldg(p + 1) - P.m)),
                           clip01(P.m + P.f * (__ldg(p + 2) - P.m)));
    } else {
        float smr = 0.0f, smg = 0.0f, smb = 0.0f;
        #pragma unroll
        for (int dy = -1; dy <= 1; dy++) {
            int yc = min(max(y + dy, 0), Hh - 1);
            #pragma unroll
            for (int dx = -1; dx <= 1; dx++) {
                int xc = min(max(x + dx, 0), Ww - 1);
                float k = (dx == 0 && dy == 0) ? (5.0f / 13.0f) : (1.0f / 13.0f);
                const float* p = img + (yc * Ww + xc) * 3;
                smr += k * __ldg(p); smg += k * __ldg(p + 1); smb += k * __ldg(p + 2);
            }
        }
        const float* p = img + (y * Ww + x) * 3;
        return make_float3(clip01(smr + P.f * (__ldg(p) - smr)),
                           clip01(smg + P.f * (__ldg(p + 1) - smg)),
                           clip01(smb + P.f * (__ldg(p + 2) - smb)));
    }
}

// ---------------- prepass kernels ----------------
__global__ void zero_sums_kernel() {
    if (threadIdx.x < BATCH) {
        g_sumA[threadIdx.x] = 0.0f;
        g_sumB[threadIdx.x] = 0.0f;
    }
}

__global__ void meanA_kernel(const float* __restrict__ in, const int* __restrict__ ops) {
    const int b = blockIdx.y;
    if (__ldg(&ops[b * 2]) != 6) return;
    const float* img = in + (size_t)b * NELEM;
    float acc = 0.0f;
    const int stride = gridDim.x * blockDim.x;
    for (int i = blockIdx.x * blockDim.x + threadIdx.x; i < NELEM; i += stride)
        acc += __ldg(&img[i]);
    __shared__ float sh[256];
    sh[threadIdx.x] = acc;
    __syncthreads();
    for (int off = 128; off > 0; off >>= 1) {
        if (threadIdx.x < off) sh[threadIdx.x] += sh[threadIdx.x + off];
        __syncthreads();
    }
    if (threadIdx.x == 0) atomicAdd(&g_sumA[b], sh[0]);
}

__global__ void meanB_kernel(const float* __restrict__ in, const int* __restrict__ ops,
                             const int* __restrict__ signs) {
    const int b = blockIdx.y;
    if (__ldg(&ops[b * 2 + 1]) != 6) return;
    L0P P;
    P.op = __ldg(&ops[b * 2]);
    float s0 = 2.0f * (float)__ldg(&signs[b * 2]) - 1.0f;
    affineCoef(P.op, s0, P.A, P.Bc, P.TX, P.C, P.D, P.TY);
    P.f = (s0 > 0.0f) ? ENHv : (1.0f / ENHv);
    P.m = g_sumA[b] * INV_NELEM;
    const float* img = in + (size_t)b * NELEM;
    float acc = 0.0f;
    const int stride = gridDim.x * blockDim.x;
    for (int p = blockIdx.x * blockDim.x + threadIdx.x; p < NPIX; p += stride) {
        float3 v = evalL0g(img, P, p >> 9, p & 511);
        acc += v.x + v.y + v.z;
    }
    __shared__ float sh[256];
    sh[threadIdx.x] = acc;
    __syncthreads();
    for (int off = 128; off > 0; off >>= 1) {
        if (threadIdx.x < off) sh[threadIdx.x] += sh[threadIdx.x + off];
        __syncthreads();
    }
    if (threadIdx.x == 0) atomicAdd(&g_sumB[b], sh[0]);
}

// ---------------- fused main kernel (two-stage smem pipeline) ----------------
// grid (32, 32, BATCH), block 256. One thread = one output pixel of a 16x16 tile.
__global__ void __launch_bounds__(256) fused2_kernel(
        const float* __restrict__ in, float* __restrict__ out,
        const int* __restrict__ ops, const int* __restrict__ signs) {
    __shared__ float sRaw[RAW_P * RAW_P * 3];   // 12 KB
    __shared__ float sL0[L0_P * L0_P * 3];      // 6.75 KB

    const int b = blockIdx.z;
    const int tid = threadIdx.x;
    const int X0 = blockIdx.x * TS;
    const int Y0 = blockIdx.y * TS;

    const int op0 = __ldg(&ops[b * 2]);
    const int op1 = __ldg(&ops[b * 2 + 1]);
    const float s0 = 2.0f * (float)__ldg(&signs[b * 2]) - 1.0f;
    const float s1 = 2.0f * (float)__ldg(&signs[b * 2 + 1]) - 1.0f;
    const float f0 = (s0 > 0.0f) ? ENHv : (1.0f / ENHv);
    const float f1 = (s1 > 0.0f) ? ENHv : (1.0f / ENHv);
    float a0, b0, tx0, c0, d0, ty0, a1, b1, tx1, c1, d1, ty1;
    affineCoef(op0, s0, a0, b0, tx0, c0, d0, ty0);
    affineCoef(op1, s1, a1, b1, tx1, c1, d1, ty1);
    const float m0 = g_sumA[b] * INV_NELEM;

    const float cx = 255.5f, cy = 255.5f;

    // ---- L0 integer box (global coords) needed by the outer op ----
    int gx0, gx1, gy0, gy1;
    if (op1 < 5) {
        float mnx = 1e30f, mxx = -1e30f, mny = 1e30f, mxy = -1e30f;
        #pragma unroll
        for (int k = 0; k < 4; k++) {
            float X = (float)(X0 + ((k & 1) ? (TS - 1) : 0));
            float Y = (float)(Y0 + ((k & 2) ? (TS - 1) : 0));
            float xi = a1 * (X - cx) + b1 * (Y - cy) + tx1 + cx;
            float yi = c1 * (X - cx) + d1 * (Y - cy) + ty1 + cy;
            mnx = fminf(mnx, xi); mxx = fmaxf(mxx, xi);
            mny = fminf(mny, yi); mxy = fmaxf(mxy, yi);
        }
        gx0 = (int)floorf(mnx) - 1; gx1 = (int)floorf(mxx) + 2;
        gy0 = (int)floorf(mny) - 1; gy1 = (int)floorf(mxy) + 2;
    } else if (op1 == 7) {
        gx0 = X0 - 1; gx1 = X0 + TS; gy0 = Y0 - 1; gy1 = Y0 + TS;
    } else {
        gx0 = X0; gx1 = X0 + TS - 1; gy0 = Y0; gy1 = Y0 + TS - 1;
    }
    // clamp box INTO the image in both directions (footprint may be fully outside)
    gx0 = min(max(gx0, 0), Ww - 1); gy0 = min(max(gy0, 0), Hh - 1);
    gx1 = min(gx1, Ww - 1); gy1 = min(gy1, Hh - 1);
    gx1 = max(gx1, gx0); gy1 = max(gy1, gy0);
    gx1 = min(gx1, gx0 + L0_P - 1); gy1 = min(gy1, gy0 + L0_P - 1);
    const int l0W = gx1 - gx0 + 1, l0H = gy1 - gy0 + 1;

    // ---- raw input box (global coords) needed to compute L0 over its box ----
    int rx0, rx1, ry0, ry1;
    if (op0 < 5) {
        float mnx = 1e30f, mxx = -1e30f, mny = 1e30f, mxy = -1e30f;
        #pragma unroll
        for (int k = 0; k < 4; k++) {
            float X = (float)((k & 1) ? gx1 : gx0);
            float Y = (float)((k & 2) ? gy1 : gy0);
            float xi = a0 * (X - cx) + b0 * (Y - cy) + tx0 + cx;
            float yi = c0 * (X - cx) + d0 * (Y - cy) + ty0 + cy;
            mnx = fminf(mnx, xi); mxx = fmaxf(mxx, xi);
            mny = fminf(mny, yi); mxy = fmaxf(mxy, yi);
        }
        rx0 = (int)floorf(mnx) - 1; rx1 = (int)floorf(mxx) + 2;
        ry0 = (int)floorf(mny) - 1; ry1 = (int)floorf(mxy) + 2;
    } else if (op0 == 7) {
        rx0 = gx0 - 1; rx1 = gx1 + 1; ry0 = gy0 - 1; ry1 = gy1 + 1;
    } else {
        rx0 = gx0; rx1 = gx1; ry0 = gy0; ry1 = gy1;
    }
    // clamp raw box INTO the image in both directions
    rx0 = min(max(rx0, 0), Ww - 1); ry0 = min(max(ry0, 0), Hh - 1);
    rx1 = min(rx1, Ww - 1); ry1 = min(ry1, Hh - 1);
    rx1 = max(rx1, rx0); ry1 = max(ry1, ry0);
    rx1 = min(rx1, rx0 + RAW_P - 1); ry1 = min(ry1, ry0 + RAW_P - 1);
    const int rawW = rx1 - rx0 + 1, rawH = ry1 - ry0 + 1;

    const float* img = in + (size_t)b * NELEM;

    // ---- stage raw box (coalesced: consecutive i -> consecutive gmem floats) ----
    const int rawW3 = rawW * 3;
    for (int i = tid; i < rawH * (RAW_P * 3); i += 256) {
        int row = i / (RAW_P * 3);
        int k = i - row * (RAW_P * 3);
        if (k < rawW3)
            sRaw[row * (RAW_P * 3) + k] =
                __ldg(&img[(ry0 + row) * (Ww * 3) + rx0 * 3 + k]);
    }
    __syncthreads();

    // ---- compute L0 on its integer box into sL0 ----
    for (int j = tid; j < l0H * L0_P; j += 256) {
        int row = j / L0_P;
        int col = j - row * L0_P;
        if (col >= l0W) continue;
        int py = gy0 + row, px = gx0 + col;
        float r0, r1, r2;
        if (op0 < 5) {
            float xi = a0 * ((float)px - cx) + b0 * ((float)py - cy) + tx0 + cx;
            float yi = c0 * ((float)px - cx) + d0 * ((float)py - cy) + ty0 + cy;
            float xf = floorf(xi), yf = floorf(yi);
            float wx = xi - xf, wy = yi - yf;
            int ix = (int)xf, iy = (int)yf;
            float w00 = (1.0f - wx) * (1.0f - wy), w10 = wx * (1.0f - wy);
            float w01 = (1.0f - wx) * wy, w11 = wx * wy;
            r0 = r1 = r2 = 0.0f;
            #pragma unroll
            for (int t = 0; t < 4; t++) {
                int ty = iy + (t >> 1), tx = ix + (t & 1);
                float w = (t == 0) ? w00 : (t == 1) ? w10 : (t == 2) ? w01 : w11;
                float v0, v1, v2;
                if ((unsigned)tx >= (unsigned)Ww || (unsigned)ty >= (unsigned)Hh) {
                    v0 = v1 = v2 = FILLv;
                } else {
                    // safety clamp into the staged box (no-op for reachable taps)
                    int sy = min(max(ty - ry0, 0), RAW_P - 1);
                    int sx = min(max(tx - rx0, 0), RAW_P - 1);
                    int o = sy * (RAW_P * 3) + sx * 3;
                    v0 = sRaw[o]; v1 = sRaw[o + 1]; v2 = sRaw[o + 2];
                }
                r0 += w * v0; r1 += w * v1; r2 += w * v2;
            }
        } else if (op0 == 5) {
            int o = (py - ry0) * (RAW_P * 3) + (px - rx0) * 3;
            r0 = clip01(f0 * sRaw[o]);
            r1 = clip01(f0 * sRaw[o + 1]);
            r2 = clip01(f0 * sRaw[o + 2]);
        } else if (op0 == 6) {
            int o = (py - ry0) * (RAW_P * 3) + (px - rx0) * 3;
            r0 = clip01(m0 + f0 * (sRaw[o] - m0));
            r1 = clip01(m0 + f0 * (sRaw[o + 1] - m0));
            r2 = clip01(m0 + f0 * (sRaw[o + 2] - m0));
        } else {
            float smr = 0.0f, smg = 0.0f, smb = 0.0f;
            #pragma unroll
            for (int dy = -1; dy <= 1; dy++) {
                int yc = min(max(py + dy, 0), Hh - 1);
                #pragma unroll
                for (int dx = -1; dx <= 1; dx++) {
                    int xc = min(max(px + dx, 0), Ww - 1);
                    float k = (dx == 0 && dy == 0) ? (5.0f / 13.0f) : (1.0f / 13.0f);
                    int o = (yc - ry0) * (RAW_P * 3) + (xc - rx0) * 3;
                    smr += k * sRaw[o]; smg += k * sRaw[o + 1]; smb += k * sRaw[o + 2];
                }
            }
            int o = (py - ry0) * (RAW_P * 3) + (px - rx0) * 3;
            r0 = clip01(smr + f0 * (sRaw[o] - smr));
            r1 = clip01(smg + f0 * (sRaw[o + 1] - smg));
            r2 = clip01(smb + f0 * (sRaw[o + 2] - smb));
        }
        int o = (row * L0_P + col) * 3;
        sL0[o] = r0; sL0[o + 1] = r1; sL0[o + 2] = r2;
    }
    __syncthreads();

    // ---- outer op from sL0, write result ----
    const int x = X0 + (tid & 15);
    const int y = Y0 + (tid >> 4);
    float r0, r1, r2;

    if (op1 < 5) {
        float xi = a1 * ((float)x - cx) + b1 * ((float)y - cy) + tx1 + cx;
        float yi = c1 * ((float)x - cx) + d1 * ((float)y - cy) + ty1 + cy;
        float xf = floorf(xi), yf = floorf(yi);
        float wx = xi - xf, wy = yi - yf;
        int ix = (int)xf, iy = (int)yf;
        float w00 = (1.0f - wx) * (1.0f - wy), w10 = wx * (1.0f - wy);
        float w01 = (1.0f - wx) * wy, w11 = wx * wy;
        r0 = r1 = r2 = 0.0f;
        #pragma unroll
        for (int t = 0; t < 4; t++) {
            int ty = iy + (t >> 1), tx = ix + (t & 1);
            float w = (t == 0) ? w00 : (t == 1) ? w10 : (t == 2) ? w01 : w11;
            float v0, v1, v2;
            if ((unsigned)tx >= (unsigned)Ww || (unsigned)ty >= (unsigned)Hh) {
                v0 = v1 = v2 = FILLv;
            } else {
                // safety clamp into the L0 box (no-op for reachable taps)
                int sy = min(max(ty - gy0, 0), L0_P - 1);
                int sx = min(max(tx - gx0, 0), L0_P - 1);
                int o = (sy * L0_P + sx) * 3;
                v0 = sL0[o]; v1 = sL0[o + 1]; v2 = sL0[o + 2];
            }
            r0 += w * v0; r1 += w * v1; r2 += w * v2;
        }
    } else if (op1 == 5) {
        int o = ((y - gy0) * L0_P + (x - gx0)) * 3;
        r0 = clip01(f1 * sL0[o]);
        r1 = clip01(f1 * sL0[o + 1]);
        r2 = clip01(f1 * sL0[o + 2]);
    } else if (op1 == 6) {
        const float m1 = g_sumB[b] * INV_NELEM;
        int o = ((y - gy0) * L0_P + (x - gx0)) * 3;
        r0 = clip01(m1 + f1 * (sL0[o] - m1));
        r1 = clip01(m1 + f1 * (sL0[o + 1] - m1));
        r2 = clip01(m1 + f1 * (sL0[o + 2] - m1));
    } else {
        float smr = 0.0f, smg = 0.0f, smb = 0.0f;
        #pragma unroll
        for (int dy = -1; dy <= 1; dy++) {
            int yc = min(max(y + dy, 0), Hh - 1);
            #pragma unroll
            for (int dx = -1; dx <= 1; dx++) {
                int xc = min(max(x + dx, 0), Ww - 1);
                float k = (dx == 0 && dy == 0) ? (5.0f / 13.0f) : (1.0f / 13.0f);
                int o = ((yc - gy0) * L0_P + (xc - gx0)) * 3;
                smr += k * sL0[o]; smg += k * sL0[o + 1]; smb += k * sL0[o + 2];
            }
        }
        int o = ((y - gy0) * L0_P + (x - gx0)) * 3;
        r0 = clip01(smr + f1 * (sL0[o] - smr));
        r1 = clip01(smg + f1 * (sL0[o + 1] - smg));
        r2 = clip01(smb + f1 * (sL0[o + 2] - smb));
    }

    float* o = out + (size_t)b * NELEM + (y * Ww + x) * 3;
    o[0] = r0; o[1] = r1; o[2] = r2;
}

extern "C" void kernel_launch(void* const* d_in, const int* in_sizes, int n_in,
                              void* d_out, int out_size) {
    const float* images = (const float*)d_in[0];
    const int* op_ids = (const int*)d_in[1];
    const int* sgn = (const int*)d_in[2];
    float* out = (float*)d_out;

    zero_sums_kernel<<<1, 64>>>();
    meanA_kernel<<<dim3(64, BATCH), 256>>>(images, op_ids);
    meanB_kernel<<<dim3(64, BATCH), 256>>>(images, op_ids, sgn);
    fused2_kernel<<<dim3(Ww / TS, Hh / TS, BATCH), 256>>>(images, out, op_ids, sgn);
}

// round 5
// speedup vs baseline: 1.8425x; 1.8425x over previous
#include <cuda_runtime.h>
#include <math.h>

#define BATCH 64
#define Hh 512
#define Ww 512
#define NPIX (Hh * Ww)
#define NELEM (NPIX * 3)
#define MAGv 0.5f
#define ENHv (1.0f + 0.9f * MAGv)      // 1.45
#define FILLv 0.5f
#define INV_NELEM (1.0f / (float)NELEM)
#define TPB 128

__device__ float g_buf[(size_t)BATCH * NELEM];   // 201 MB intermediate
__device__ float g_sumA[BATCH];   // sum of raw input (op0 == contrast)
__device__ float g_sumB[BATCH];   // sum of layer-0 output (op1 == contrast)

__device__ __forceinline__ float clip01(float v) {
    return fminf(fmaxf(v, 0.0f), 1.0f);
}

// pointwise layer-0 transform (op 5 = brightness, op 6 = contrast)
__device__ __forceinline__ float pw0(float v, int op, float f, float m) {
    return (op == 5) ? clip01(f * v) : clip01(m + f * (v - m));
}

__device__ __forceinline__ void affineCoef(int op, float s,
        float& A, float& B, float& TX, float& C, float& D, float& TY) {
    A = 1.0f; B = 0.0f; TX = 0.0f; C = 0.0f; D = 1.0f; TY = 0.0f;
    if (op == 0) {
        float th = s * (30.0f * MAGv) * (3.14159265358979323846f / 180.0f);
        float si, co;
        sincosf(th, &si, &co);
        A = co; B = si; C = -si; D = co;
    } else if (op == 1) {
        B = -(s * 0.3f * MAGv);
    } else if (op == 2) {
        C = -(s * 0.3f * MAGv);
    } else if (op == 3) {
        TX = -(s * 0.3f * MAGv * (float)Ww);
    } else if (op == 4) {
        TY = -(s * 0.3f * MAGv * (float)Hh);
    }
}

// ---------------- prepass kernels ----------------
__global__ void zero_sums_kernel() {
    if (threadIdx.x < BATCH) {
        g_sumA[threadIdx.x] = 0.0f;
        g_sumB[threadIdx.x] = 0.0f;
    }
}

// sum of raw input for images with op0 == contrast
__global__ void meanA_kernel(const float* __restrict__ in, const int* __restrict__ ops) {
    const int b = blockIdx.y;
    if (__ldg(&ops[b * 2]) != 6) return;
    const float* img = in + (size_t)b * NELEM;
    float acc = 0.0f;
    const int stride = gridDim.x * blockDim.x;
    for (int i = blockIdx.x * blockDim.x + threadIdx.x; i < NELEM; i += stride)
        acc += __ldg(&img[i]);
    __shared__ float sh[256];
    sh[threadIdx.x] = acc;
    __syncthreads();
    for (int off = 128; off > 0; off >>= 1) {
        if (threadIdx.x < off) sh[threadIdx.x] += sh[threadIdx.x + off];
        __syncthreads();
    }
    if (threadIdx.x == 0) atomicAdd(&g_sumA[b], sh[0]);
}

// sum of pointwise-L0 output for images with op0 in {5,6} AND op1 == contrast
__global__ void meanB_pw_kernel(const float* __restrict__ in, const int* __restrict__ ops,
                                const int* __restrict__ signs) {
    const int b = blockIdx.y;
    const int op0 = __ldg(&ops[b * 2]);
    if (!((op0 == 5 || op0 == 6) && __ldg(&ops[b * 2 + 1]) == 6)) return;
    const float s0 = 2.0f * (float)__ldg(&signs[b * 2]) - 1.0f;
    const float f0 = (s0 > 0.0f) ? ENHv : (1.0f / ENHv);
    const float m0 = g_sumA[b] * INV_NELEM;
    const float* img = in + (size_t)b * NELEM;
    float acc = 0.0f;
    const int stride = gridDim.x * blockDim.x;
    for (int i = blockIdx.x * blockDim.x + threadIdx.x; i < NELEM; i += stride)
        acc += pw0(__ldg(&img[i]), op0, f0, m0);
    __shared__ float sh[256];
    sh[threadIdx.x] = acc;
    __syncthreads();
    for (int off = 128; off > 0; off >>= 1) {
        if (threadIdx.x < off) sh[threadIdx.x] += sh[threadIdx.x + off];
        __syncthreads();
    }
    if (threadIdx.x == 0) atomicAdd(&g_sumB[b], sh[0]);
}

// ---------------- pass 1: heavy op0 (affine / sharpness) ----------------
// grid (Hh, BATCH), block 128. One block = one image row (512 px).
__global__ void __launch_bounds__(TPB) pass1_kernel(
        const float* __restrict__ in, float* __restrict__ dout,
        const int* __restrict__ ops, const int* __restrict__ signs) {
    __shared__ float srow[Ww * 3];   // 6 KB staged output row
    __shared__ float sred[TPB];

    const int b = blockIdx.y;
    const int op0 = __ldg(&ops[b * 2]);
    if (op0 == 5 || op0 == 6) return;          // route A: handled in pass 2
    const int op1 = __ldg(&ops[b * 2 + 1]);
    const int y = blockIdx.x;
    const int tid = threadIdx.x;

    const float s0 = 2.0f * (float)__ldg(&signs[b * 2]) - 1.0f;
    const float s1 = 2.0f * (float)__ldg(&signs[b * 2 + 1]) - 1.0f;
    const float f0 = (s0 > 0.0f) ? ENHv : (1.0f / ENHv);
    const float f1 = (s1 > 0.0f) ? ENHv : (1.0f / ENHv);

    const float* img = in + (size_t)b * NELEM;
    const bool wantSum = (op1 == 6);
    float acc = 0.0f;

    if (op0 < 5) {
        float a, bb, tx, c, d, ty;
        affineCoef(op0, s0, a, bb, tx, c, d, ty);
        const float cx = 255.5f, cy = 255.5f;
        const float yb = (float)y - cy;
        const float xiB = bb * yb + tx + cx;
        const float yiB = d * yb + ty + cy;
        #pragma unroll
        for (int j = 0; j < 4; j++) {
            const int x = j * TPB + tid;
            const float xd = (float)x - cx;
            const float xi = a * xd + xiB;
            const float yi = c * xd + yiB;
            const float xf = floorf(xi), yf = floorf(yi);
            const float wx = xi - xf, wy = yi - yf;
            const int ix = (int)xf, iy = (int)yf;
            const float w00 = (1.0f - wx) * (1.0f - wy), w10 = wx * (1.0f - wy);
            const float w01 = (1.0f - wx) * wy, w11 = wx * wy;
            float r0 = 0.0f, r1 = 0.0f, r2 = 0.0f;
            #pragma unroll
            for (int t = 0; t < 4; t++) {
                const int ty2 = iy + (t >> 1), tx2 = ix + (t & 1);
                const float w = (t == 0) ? w00 : (t == 1) ? w10 : (t == 2) ? w01 : w11;
                if ((unsigned)tx2 >= (unsigned)Ww || (unsigned)ty2 >= (unsigned)Hh) {
                    r0 += w * FILLv; r1 += w * FILLv; r2 += w * FILLv;
                } else {
                    const float* p = img + (ty2 * Ww + tx2) * 3;
                    r0 += w * __ldg(p); r1 += w * __ldg(p + 1); r2 += w * __ldg(p + 2);
                }
            }
            srow[x * 3] = r0; srow[x * 3 + 1] = r1; srow[x * 3 + 2] = r2;
            if (wantSum) acc += r0 + r1 + r2;
        }
    } else {   // op0 == 7 : sharpness
        const int ym = max(y - 1, 0), yp = min(y + 1, Hh - 1);
        #pragma unroll
        for (int j = 0; j < 4; j++) {
            const int x = j * TPB + tid;
            const int xm = max(x - 1, 0), xp = min(x + 1, Ww - 1);
            const float k1 = 1.0f / 13.0f, k5 = 5.0f / 13.0f;
            #pragma unroll
            for (int ch = 0; ch < 3; ch++) {
                const float* rm = img + ym * (Ww * 3) + ch;
                const float* rc = img + y * (Ww * 3) + ch;
                const float* rp = img + yp * (Ww * 3) + ch;
                float sm = k1 * (__ldg(rm + xm * 3) + __ldg(rm + x * 3) + __ldg(rm + xp * 3)
                               + __ldg(rc + xm * 3) + __ldg(rc + xp * 3)
                               + __ldg(rp + xm * 3) + __ldg(rp + x * 3) + __ldg(rp + xp * 3))
                         + k5 * __ldg(rc + x * 3);
                float cv = __ldg(rc + x * 3);
                float v = clip01(sm + f0 * (cv - sm));
                srow[x * 3 + ch] = v;
                if (wantSum) acc += v;
            }
        }
    }
    __syncthreads();

    // vectorized writeout; fold op1 == brightness
    const bool bright = (op1 == 5);
    float* dst = (bright ? dout : g_buf) + (size_t)b * NELEM + y * (Ww * 3);
    const float4* s4 = (const float4*)srow;
    float4* d4 = (float4*)dst;
    for (int i = tid; i < (Ww * 3) / 4; i += TPB) {
        float4 v = s4[i];
        if (bright) {
            v.x = clip01(f1 * v.x); v.y = clip01(f1 * v.y);
            v.z = clip01(f1 * v.z); v.w = clip01(f1 * v.w);
        }
        d4[i] = v;
    }

    if (wantSum) {
        sred[tid] = acc;
        __syncthreads();
        for (int off = TPB / 2; off > 0; off >>= 1) {
            if (tid < off) sred[tid] += sred[tid + off];
            __syncthreads();
        }
        if (tid == 0) atomicAdd(&g_sumB[b], sred[0]);
    }
}

// ---------------- pass 2 ----------------
// grid (Hh, BATCH), block 128.
__global__ void __launch_bounds__(TPB) pass2_kernel(
        const float* __restrict__ in, float* __restrict__ dout,
        const int* __restrict__ ops, const int* __restrict__ signs) {
    __shared__ float srow[Ww * 3];

    const int b = blockIdx.y;
    const int op0 = __ldg(&ops[b * 2]);
    const int op1 = __ldg(&ops[b * 2 + 1]);
    const bool routeA = (op0 == 5 || op0 == 6);
    if (!routeA && op1 == 5) return;           // fully handled in pass 1

    const int y = blockIdx.x;
    const int tid = threadIdx.x;
    const float s0 = 2.0f * (float)__ldg(&signs[b * 2]) - 1.0f;
    const float s1 = 2.0f * (float)__ldg(&signs[b * 2 + 1]) - 1.0f;
    const float f0 = (s0 > 0.0f) ? ENHv : (1.0f / ENHv);
    const float f1 = (s1 > 0.0f) ? ENHv : (1.0f / ENHv);
    const float m0 = g_sumA[b] * INV_NELEM;

    const float* src = (routeA ? in : g_buf) + (size_t)b * NELEM;
    float* out = dout + (size_t)b * NELEM;

    if (op1 == 5 || op1 == 6) {
        // dense vector path (op1==5 only reachable when routeA)
        const float m1 = g_sumB[b] * INV_NELEM;
        const float4* s4 = (const float4*)(src + y * (Ww * 3));
        float4* d4 = (float4*)(out + y * (Ww * 3));
        for (int i = tid; i < (Ww * 3) / 4; i += TPB) {
            float4 v = s4[i];
            if (routeA) {
                v.x = pw0(v.x, op0, f0, m0); v.y = pw0(v.y, op0, f0, m0);
                v.z = pw0(v.z, op0, f0, m0); v.w = pw0(v.w, op0, f0, m0);
            }
            if (op1 == 5) {
                v.x = clip01(f1 * v.x); v.y = clip01(f1 * v.y);
                v.z = clip01(f1 * v.z); v.w = clip01(f1 * v.w);
            } else {
                v.x = clip01(m1 + f1 * (v.x - m1)); v.y = clip01(m1 + f1 * (v.y - m1));
                v.z = clip01(m1 + f1 * (v.z - m1)); v.w = clip01(m1 + f1 * (v.w - m1));
            }
            d4[i] = v;
        }
        return;
    }

    // gather path: op1 affine or sharpness; L0 value = maybe-pointwise(src)
    if (op1 < 5) {
        float a, bb, tx, c, d, ty;
        affineCoef(op1, s1, a, bb, tx, c, d, ty);
        const float cx = 255.5f, cy = 255.5f;
        const float yb = (float)y - cy;
        const float xiB = bb * yb + tx + cx;
        const float yiB = d * yb + ty + cy;
        #pragma unroll
        for (int j = 0; j < 4; j++) {
            const int x = j * TPB + tid;
            const float xd = (float)x - cx;
            const float xi = a * xd + xiB;
            const float yi = c * xd + yiB;
            const float xf = floorf(xi), yf = floorf(yi);
            const float wx = xi - xf, wy = yi - yf;
            const int ix = (int)xf, iy = (int)yf;
            const float w00 = (1.0f - wx) * (1.0f - wy), w10 = wx * (1.0f - wy);
            const float w01 = (1.0f - wx) * wy, w11 = wx * wy;
            float r0 = 0.0f, r1 = 0.0f, r2 = 0.0f;
            #pragma unroll
            for (int t = 0; t < 4; t++) {
                const int ty2 = iy + (t >> 1), tx2 = ix + (t & 1);
                const float w = (t == 0) ? w00 : (t == 1) ? w10 : (t == 2) ? w01 : w11;
                if ((unsigned)tx2 >= (unsigned)Ww || (unsigned)ty2 >= (unsigned)Hh) {
                    r0 += w * FILLv; r1 += w * FILLv; r2 += w * FILLv;
                } else {
                    const float* p = src + (ty2 * Ww + tx2) * 3;
                    float v0 = __ldg(p), v1 = __ldg(p + 1), v2 = __ldg(p + 2);
                    if (routeA) {
                        v0 = pw0(v0, op0, f0, m0);
                        v1 = pw0(v1, op0, f0, m0);
                        v2 = pw0(v2, op0, f0, m0);
                    }
                    r0 += w * v0; r1 += w * v1; r2 += w * v2;
                }
            }
            srow[x * 3] = r0; srow[x * 3 + 1] = r1; srow[x * 3 + 2] = r2;
        }
    } else {   // op1 == 7 : sharpness of L0
        const int ym = max(y - 1, 0), yp = min(y + 1, Hh - 1);
        #pragma unroll
        for (int j = 0; j < 4; j++) {
            const int x = j * TPB + tid;
            const int xm = max(x - 1, 0), xp = min(x + 1, Ww - 1);
            const float k1 = 1.0f / 13.0f, k5 = 5.0f / 13.0f;
            #pragma unroll
            for (int ch = 0; ch < 3; ch++) {
                const float* rm = src + ym * (Ww * 3) + ch;
                const float* rc = src + y * (Ww * 3) + ch;
                const float* rp = src + yp * (Ww * 3) + ch;
                float t0 = __ldg(rm + xm * 3), t1 = __ldg(rm + x * 3), t2 = __ldg(rm + xp * 3);
                float t3 = __ldg(rc + xm * 3), t4 = __ldg(rc + x * 3), t5 = __ldg(rc + xp * 3);
                float t6 = __ldg(rp + xm * 3), t7 = __ldg(rp + x * 3), t8 = __ldg(rp + xp * 3);
                if (routeA) {
                    t0 = pw0(t0, op0, f0, m0); t1 = pw0(t1, op0, f0, m0);
                    t2 = pw0(t2, op0, f0, m0); t3 = pw0(t3, op0, f0, m0);
                    t4 = pw0(t4, op0, f0, m0); t5 = pw0(t5, op0, f0, m0);
                    t6 = pw0(t6, op0, f0, m0); t7 = pw0(t7, op0, f0, m0);
                    t8 = pw0(t8, op0, f0, m0);
                }
                float sm = k1 * (t0 + t1 + t2 + t3 + t5 + t6 + t7 + t8) + k5 * t4;
                srow[x * 3 + ch] = clip01(sm + f1 * (t4 - sm));
            }
        }
    }
    __syncthreads();

    const float4* s4 = (const float4*)srow;
    float4* d4 = (float4*)(out + y * (Ww * 3));
    for (int i = tid; i < (Ww * 3) / 4; i += TPB)
        d4[i] = s4[i];
}

extern "C" void kernel_launch(void* const* d_in, const int* in_sizes, int n_in,
                              void* d_out, int out_size) {
    const float* images = (const float*)d_in[0];
    const int* op_ids = (const int*)d_in[1];
    const int* sgn = (const int*)d_in[2];
    float* out = (float*)d_out;

    zero_sums_kernel<<<1, 64>>>();
    meanA_kernel<<<dim3(64, BATCH), 256>>>(images, op_ids);
    meanB_pw_kernel<<<dim3(64, BATCH), 256>>>(images, op_ids, sgn);
    pass1_kernel<<<dim3(Hh, BATCH), TPB>>>(images, out, op_ids, sgn);
    pass2_kernel<<<dim3(Hh, BATCH), TPB>>>(images, out, op_ids, sgn);
}